// round 6
// baseline (speedup 1.0000x reference)
#include <cuda_runtime.h>
#include <math.h>

#define BATCH 4
#define TQL   128
#define TKL   512
#define ND    512
#define OD    512

// Scratch (device globals -- no allocation allowed)
__device__ __align__(16) float g_attq[BATCH * TQL * ND];
__device__ __align__(16) float g_ctx [BATCH * TQL * ND];

__device__ __forceinline__ float fast_tanh(float x) {
    float y;
    asm("tanh.approx.f32 %0, %1;" : "=f"(y) : "f"(x));
    return y;
}

// ----------------------------------------------------------------------------
// Tiled NT GEMM: C[m,n] = act( sum_k A[m,k] * B[n,k] + bias[n] )
// BM=32, BN=64, BK=16, 256 threads, 2x4 micro-tile per thread.
// A columns [0,ND) come from A0; if SECOND_IS_CTX, columns [ND,K) come from g_ctx.
// If OUT_ATTQ, C is g_attq (Cext ignored).
// ----------------------------------------------------------------------------
template <int K, bool DO_TANH, bool SECOND_IS_CTX, bool OUT_ATTQ>
__global__ __launch_bounds__(256) void gemm_nt(
    const float* __restrict__ A0,
    const float* __restrict__ B,
    const float* __restrict__ bias,
    float* __restrict__ Cext, int N)
{
    float* C = OUT_ATTQ ? g_attq : Cext;

    __shared__ float As[32][17];
    __shared__ float Bs[64][17];

    const int tid = threadIdx.x;
    const int ty  = tid >> 4;   // 0..15
    const int tx  = tid & 15;   // 0..15
    const int m0  = blockIdx.y * 32;
    const int n0  = blockIdx.x * 64;

    float acc[2][4];
#pragma unroll
    for (int i = 0; i < 2; i++)
#pragma unroll
        for (int j = 0; j < 4; j++) acc[i][j] = 0.f;

    const int nkt = K >> 4;
    for (int kt = 0; kt < nkt; kt++) {
        const int kbase = kt << 4;

        const float* Asrc;
        int astride, koff;
        if (SECOND_IS_CTX && kbase >= ND) {
            Asrc = g_ctx; astride = ND; koff = kbase - ND;
        } else {
            Asrc = A0; astride = SECOND_IS_CTX ? ND : K; koff = kbase;
        }

        // Load A tile: 32x16 = 512 elements, 2 per thread
#pragma unroll
        for (int e = 0; e < 2; e++) {
            int idx = tid + 256 * e;
            int r = idx >> 4, c = idx & 15;
            As[r][c] = Asrc[(size_t)(m0 + r) * astride + koff + c];
        }
        // Load B tile: 64x16 = 1024 elements, 4 per thread
#pragma unroll
        for (int e = 0; e < 4; e++) {
            int idx = tid + 256 * e;
            int r = idx >> 4, c = idx & 15;
            Bs[r][c] = B[(size_t)(n0 + r) * K + kbase + c];
        }
        __syncthreads();

#pragma unroll
        for (int kk = 0; kk < 16; kk++) {
            float a0 = As[ty * 2 + 0][kk];
            float a1 = As[ty * 2 + 1][kk];
#pragma unroll
            for (int j = 0; j < 4; j++) {
                float bv = Bs[tx * 4 + j][kk];
                acc[0][j] += a0 * bv;
                acc[1][j] += a1 * bv;
            }
        }
        __syncthreads();
    }

#pragma unroll
    for (int i = 0; i < 2; i++) {
        const int m = m0 + ty * 2 + i;
#pragma unroll
        for (int j = 0; j < 4; j++) {
            const int n = n0 + tx * 4 + j;
            float v = acc[i][j] + bias[n];
            if (DO_TANH) v = tanhf(v);   // accurate tanh on final output
            C[(size_t)m * N + n] = v;
        }
    }
}

// ----------------------------------------------------------------------------
// Fused Bahdanau scores + softmax + context.
// One block = one batch, 4 consecutive queries. 256 threads (8 warps).
// Phase A: warp w computes scores for k = w, w+8, ...   (MUFU-tanh bound)
// Phase B: warps 0..3 do softmax for q = wid, write probs to gmem.
// Phase C: all threads accumulate context = probs @ values, 2 cols/thread.
// ----------------------------------------------------------------------------
__global__ __launch_bounds__(256) void bahdanau_attn(
    const float* __restrict__ keys,     // [B, TK, N]
    const float* __restrict__ values,   // [B, TK, N]
    const float* __restrict__ w_att,    // [N]
    const float* __restrict__ b_att,    // [1]
    float* __restrict__ probs_out)      // [B, TQ, TK]
{
    __shared__ float s_sc[4][TKL];      // scores -> exp -> probs (8 KB)

    const int tid  = threadIdx.x;
    const int wid  = tid >> 5;
    const int lane = tid & 31;
    const int b    = blockIdx.x >> 5;          // 32 blocks per batch
    const int q0   = (blockIdx.x & 31) << 2;   // 4 queries per block

    // Register-resident w_att and att_query rows.
    // Lane owns n = 4*lane + 128*i + j  (i in 0..3, j in 0..3) -> coalesced float4.
    float wreg[16];
    float areg[4][16];
#pragma unroll
    for (int i = 0; i < 4; i++) {
        float4 w4 = *(const float4*)(w_att + i * 128 + lane * 4);
        wreg[i * 4 + 0] = w4.x; wreg[i * 4 + 1] = w4.y;
        wreg[i * 4 + 2] = w4.z; wreg[i * 4 + 3] = w4.w;
#pragma unroll
        for (int q = 0; q < 4; q++) {
            float4 a4 = *(const float4*)(g_attq + (size_t)(b * TQL + q0 + q) * ND + i * 128 + lane * 4);
            areg[q][i * 4 + 0] = a4.x; areg[q][i * 4 + 1] = a4.y;
            areg[q][i * 4 + 2] = a4.z; areg[q][i * 4 + 3] = a4.w;
        }
    }
    const float batt = b_att[0];
    const float* keyb = keys + (size_t)b * TKL * ND;

    // ---- Phase A: scores[q][k] = sum_n w[n] * tanh(aq[q][n] + key[k][n]) + batt
    for (int k = wid; k < TKL; k += 8) {
        const float* kr = keyb + (size_t)k * ND;
        float acc0 = 0.f, acc1 = 0.f, acc2 = 0.f, acc3 = 0.f;
#pragma unroll
        for (int i = 0; i < 4; i++) {
            float4 k4 = *(const float4*)(kr + i * 128 + lane * 4);
            float kv[4] = {k4.x, k4.y, k4.z, k4.w};
#pragma unroll
            for (int j = 0; j < 4; j++) {
                const float w = wreg[i * 4 + j];
                acc0 += w * fast_tanh(areg[0][i * 4 + j] + kv[j]);
                acc1 += w * fast_tanh(areg[1][i * 4 + j] + kv[j]);
                acc2 += w * fast_tanh(areg[2][i * 4 + j] + kv[j]);
                acc3 += w * fast_tanh(areg[3][i * 4 + j] + kv[j]);
            }
        }
#pragma unroll
        for (int off = 16; off; off >>= 1) {
            acc0 += __shfl_xor_sync(0xffffffffu, acc0, off);
            acc1 += __shfl_xor_sync(0xffffffffu, acc1, off);
            acc2 += __shfl_xor_sync(0xffffffffu, acc2, off);
            acc3 += __shfl_xor_sync(0xffffffffu, acc3, off);
        }
        if (lane == 0) {
            s_sc[0][k] = acc0 + batt;
            s_sc[1][k] = acc1 + batt;
            s_sc[2][k] = acc2 + batt;
            s_sc[3][k] = acc3 + batt;
        }
    }
    __syncthreads();

    // ---- Phase B: softmax over k for each q (one warp per q)
    if (wid < 4) {
        const int q = wid;
        float m = -1e30f;
        for (int k = lane; k < TKL; k += 32) m = fmaxf(m, s_sc[q][k]);
#pragma unroll
        for (int off = 16; off; off >>= 1) m = fmaxf(m, __shfl_xor_sync(0xffffffffu, m, off));
        float s = 0.f;
        for (int k = lane; k < TKL; k += 32) {
            float e = __expf(s_sc[q][k] - m);
            s_sc[q][k] = e;
            s += e;
        }
#pragma unroll
        for (int off = 16; off; off >>= 1) s += __shfl_xor_sync(0xffffffffu, s, off);
        const float inv = 1.0f / s;
        float* pout = probs_out + (size_t)(b * TQL + q0 + q) * TKL;
        for (int k = lane; k < TKL; k += 32) {
            float p = s_sc[q][k] * inv;
            s_sc[q][k] = p;
            pout[k] = p;
        }
    }
    __syncthreads();

    // ---- Phase C: context[q][n] = sum_k probs[q][k] * values[k][n]
    const float* valb = values + (size_t)b * TKL * ND;
    const int n0 = tid * 2;
    float c0[4] = {0.f, 0.f, 0.f, 0.f};
    float c1[4] = {0.f, 0.f, 0.f, 0.f};
#pragma unroll 4
    for (int k = 0; k < TKL; k++) {
        float2 v = *(const float2*)(valb + (size_t)k * ND + n0);
#pragma unroll
        for (int q = 0; q < 4; q++) {
            float p = s_sc[q][k];
            c0[q] += p * v.x;
            c1[q] += p * v.y;
        }
    }
#pragma unroll
    for (int q = 0; q < 4; q++) {
        float* cp = g_ctx + (size_t)(b * TQL + q0 + q) * ND + n0;
        cp[0] = c0[q];
        cp[1] = c1[q];
    }
}

// ----------------------------------------------------------------------------
// Launch: 3 kernels, all graph-capturable, no host sync / alloc.
// Inputs (metadata order): query, keys, values, W_q, b_q, w_att, b_att, W_out, b_out
// Output layout: out [B*TQ*OD] followed by probs [B*TQ*TK].
// ----------------------------------------------------------------------------
extern "C" void kernel_launch(void* const* d_in, const int* in_sizes, int n_in,
                              void* d_out, int out_size)
{
    const float* query  = (const float*)d_in[0];
    const float* keys   = (const float*)d_in[1];
    const float* values = (const float*)d_in[2];
    const float* W_q    = (const float*)d_in[3];
    const float* b_q    = (const float*)d_in[4];
    const float* w_att  = (const float*)d_in[5];
    const float* b_att  = (const float*)d_in[6];
    const float* W_out  = (const float*)d_in[7];
    const float* b_out  = (const float*)d_in[8];

    float* out   = (float*)d_out;
    float* probs = out + (size_t)BATCH * TQL * OD;

    const int M = BATCH * TQL;  // 512

    // 1) att_query = query @ W_q^T + b_q   -> g_attq   (M=512, N=512, K=512)
    gemm_nt<ND, false, false, true>
        <<<dim3(ND / 64, M / 32), 256>>>(query, W_q, b_q, out /*unused*/, ND);

    // 2) fused scores + softmax + context; writes probs and g_ctx
    bahdanau_attn<<<M / 4, 256>>>(keys, values, w_att, b_att, probs);

    // 3) out = tanh( concat(query, ctx) @ W_out^T + b_out )   (K=1024)
    gemm_nt<2 * ND, true, true, false>
        <<<dim3(OD / 64, M / 32), 256>>>(query, W_out, b_out, out, OD);
}

// round 7
// speedup vs baseline: 1.4277x; 1.4277x over previous
#include <cuda_runtime.h>
#include <math.h>

#define BATCH 4
#define TQL   128
#define TKL   512
#define ND    512
#define OD    512
#define MROWS (BATCH * TQL)   // 512

// Scratch (device globals -- no allocation allowed)
__device__ __align__(16) float g_attq[MROWS * ND];
__device__ __align__(16) float g_ctx [MROWS * ND];
__device__ __align__(16) float g_part[4 * MROWS * 512];   // split-K partials

__device__ __forceinline__ float fast_tanh(float x) {
    float y;
    asm("tanh.approx.f32 %0, %1;" : "=f"(y) : "f"(x));
    return y;
}

// ----------------------------------------------------------------------------
// Split-K NT GEMM: part[z][m][n] = sum_{k in chunk z} A[m,k] * B[n,k]
// 64x64 tile, BK=16, 256 threads, 4x4 micro-tile, double-buffered smem.
// A columns [0,ND) come from A0 (row stride ND); if SECOND_IS_CTX, columns
// [ND,K) come from g_ctx. B is [N,K] row-major (stride K).
// M = N = 512 fixed.
// ----------------------------------------------------------------------------
template <int K, int SPLITS, bool SECOND_IS_CTX>
__global__ __launch_bounds__(256, 2) void gemm_nt_splitk(
    const float* __restrict__ A0,
    const float* __restrict__ B)
{
    constexpr int CHUNK  = K / SPLITS;
    constexpr int STAGES = CHUNK / 16;

    __shared__ float As[2][16][68];   // [buf][k][m], stride 68 (16B-aligned rows)
    __shared__ float Bs[2][16][68];   // [buf][k][n]

    const int tid = threadIdx.x;
    const int r   = tid >> 2;   // 0..63 (row within tile for loads)
    const int c   = tid & 3;    // 0..3  (k-group for loads)
    const int ty  = tid >> 4;   // 0..15
    const int tx  = tid & 15;   // 0..15
    const int m0  = blockIdx.y * 64;
    const int n0  = blockIdx.x * 64;
    const int kst = blockIdx.z * CHUNK;

    float acc[4][4] = {};

    auto a_addr = [&](int kb) -> const float* {
        if (SECOND_IS_CTX && kb >= ND)
            return g_ctx + (size_t)(m0 + r) * ND + (kb - ND) + 4 * c;
        return A0 + (size_t)(m0 + r) * ND + kb + 4 * c;
    };

    // prologue: load stage 0 into registers, then smem
    float4 av = *(const float4*)a_addr(kst);
    float4 bv = *(const float4*)(B + (size_t)(n0 + r) * K + kst + 4 * c);
    {
        float a4[4] = {av.x, av.y, av.z, av.w};
        float b4[4] = {bv.x, bv.y, bv.z, bv.w};
#pragma unroll
        for (int j = 0; j < 4; j++) {
            As[0][4 * c + j][r] = a4[j];
            Bs[0][4 * c + j][r] = b4[j];
        }
    }
    __syncthreads();

    int buf = 0;
#pragma unroll 1
    for (int s = 0; s < STAGES; s++) {
        float4 anx, bnx;
        if (s + 1 < STAGES) {
            const int kb = kst + (s + 1) * 16;
            anx = *(const float4*)a_addr(kb);
            bnx = *(const float4*)(B + (size_t)(n0 + r) * K + kb + 4 * c);
        }

#pragma unroll
        for (int kk = 0; kk < 16; kk++) {
            float4 a = *(const float4*)&As[buf][kk][ty * 4];
            float4 b = *(const float4*)&Bs[buf][kk][tx * 4];
            float a4[4] = {a.x, a.y, a.z, a.w};
            float b4[4] = {b.x, b.y, b.z, b.w};
#pragma unroll
            for (int i = 0; i < 4; i++)
#pragma unroll
                for (int j = 0; j < 4; j++)
                    acc[i][j] += a4[i] * b4[j];
        }

        if (s + 1 < STAGES) {
            const int nb = buf ^ 1;
            float a4[4] = {anx.x, anx.y, anx.z, anx.w};
            float b4[4] = {bnx.x, bnx.y, bnx.z, bnx.w};
#pragma unroll
            for (int j = 0; j < 4; j++) {
                As[nb][4 * c + j][r] = a4[j];
                Bs[nb][4 * c + j][r] = b4[j];
            }
            __syncthreads();
            buf = nb;
        }
    }

    // write partial tile (vectorized float4 stores)
    float* pp = g_part + (size_t)blockIdx.z * MROWS * 512;
#pragma unroll
    for (int i = 0; i < 4; i++) {
        float4 v = make_float4(acc[i][0], acc[i][1], acc[i][2], acc[i][3]);
        *(float4*)&pp[(size_t)(m0 + ty * 4 + i) * 512 + n0 + tx * 4] = v;
    }
}

// ----------------------------------------------------------------------------
// Split-K reduction + bias (+ optional accurate tanh). 512x512 elements.
// OUT_ATTQ selects the g_attq device symbol as destination.
// ----------------------------------------------------------------------------
template <int SPLITS, bool DO_TANH, bool OUT_ATTQ>
__global__ __launch_bounds__(256) void reduce_bias(
    const float* __restrict__ bias,
    float* __restrict__ dext)
{
    float* dst = OUT_ATTQ ? g_attq : dext;
    const int idx = blockIdx.x * 256 + threadIdx.x;   // float4 index, 65536 total
    const float4* p = (const float4*)g_part;

    float4 s = p[idx];
#pragma unroll
    for (int sp = 1; sp < SPLITS; sp++) {
        float4 t = p[(size_t)sp * (MROWS * 512 / 4) + idx];
        s.x += t.x; s.y += t.y; s.z += t.z; s.w += t.w;
    }
    const float4 bb = ((const float4*)bias)[idx & (512 / 4 - 1)];
    s.x += bb.x; s.y += bb.y; s.z += bb.z; s.w += bb.w;
    if (DO_TANH) {
        s.x = tanhf(s.x); s.y = tanhf(s.y); s.z = tanhf(s.z); s.w = tanhf(s.w);
    }
    ((float4*)dst)[idx] = s;
}

// ----------------------------------------------------------------------------
// Fused Bahdanau scores + softmax + context (unchanged from passing R6 kernel;
// near the MUFU-tanh floor).
// ----------------------------------------------------------------------------
__global__ __launch_bounds__(256) void bahdanau_attn(
    const float* __restrict__ keys,
    const float* __restrict__ values,
    const float* __restrict__ w_att,
    const float* __restrict__ b_att,
    float* __restrict__ probs_out)
{
    __shared__ float s_sc[4][TKL];

    const int tid  = threadIdx.x;
    const int wid  = tid >> 5;
    const int lane = tid & 31;
    const int b    = blockIdx.x >> 5;
    const int q0   = (blockIdx.x & 31) << 2;

    float wreg[16];
    float areg[4][16];
#pragma unroll
    for (int i = 0; i < 4; i++) {
        float4 w4 = *(const float4*)(w_att + i * 128 + lane * 4);
        wreg[i * 4 + 0] = w4.x; wreg[i * 4 + 1] = w4.y;
        wreg[i * 4 + 2] = w4.z; wreg[i * 4 + 3] = w4.w;
#pragma unroll
        for (int q = 0; q < 4; q++) {
            float4 a4 = *(const float4*)(g_attq + (size_t)(b * TQL + q0 + q) * ND + i * 128 + lane * 4);
            areg[q][i * 4 + 0] = a4.x; areg[q][i * 4 + 1] = a4.y;
            areg[q][i * 4 + 2] = a4.z; areg[q][i * 4 + 3] = a4.w;
        }
    }
    const float batt = b_att[0];
    const float* keyb = keys + (size_t)b * TKL * ND;

    for (int k = wid; k < TKL; k += 8) {
        const float* kr = keyb + (size_t)k * ND;
        float acc0 = 0.f, acc1 = 0.f, acc2 = 0.f, acc3 = 0.f;
#pragma unroll
        for (int i = 0; i < 4; i++) {
            float4 k4 = *(const float4*)(kr + i * 128 + lane * 4);
            float kv[4] = {k4.x, k4.y, k4.z, k4.w};
#pragma unroll
            for (int j = 0; j < 4; j++) {
                const float w = wreg[i * 4 + j];
                acc0 += w * fast_tanh(areg[0][i * 4 + j] + kv[j]);
                acc1 += w * fast_tanh(areg[1][i * 4 + j] + kv[j]);
                acc2 += w * fast_tanh(areg[2][i * 4 + j] + kv[j]);
                acc3 += w * fast_tanh(areg[3][i * 4 + j] + kv[j]);
            }
        }
#pragma unroll
        for (int off = 16; off; off >>= 1) {
            acc0 += __shfl_xor_sync(0xffffffffu, acc0, off);
            acc1 += __shfl_xor_sync(0xffffffffu, acc1, off);
            acc2 += __shfl_xor_sync(0xffffffffu, acc2, off);
            acc3 += __shfl_xor_sync(0xffffffffu, acc3, off);
        }
        if (lane == 0) {
            s_sc[0][k] = acc0 + batt;
            s_sc[1][k] = acc1 + batt;
            s_sc[2][k] = acc2 + batt;
            s_sc[3][k] = acc3 + batt;
        }
    }
    __syncthreads();

    if (wid < 4) {
        const int q = wid;
        float m = -1e30f;
        for (int k = lane; k < TKL; k += 32) m = fmaxf(m, s_sc[q][k]);
#pragma unroll
        for (int off = 16; off; off >>= 1) m = fmaxf(m, __shfl_xor_sync(0xffffffffu, m, off));
        float s = 0.f;
        for (int k = lane; k < TKL; k += 32) {
            float e = __expf(s_sc[q][k] - m);
            s_sc[q][k] = e;
            s += e;
        }
#pragma unroll
        for (int off = 16; off; off >>= 1) s += __shfl_xor_sync(0xffffffffu, s, off);
        const float inv = 1.0f / s;
        float* pout = probs_out + (size_t)(b * TQL + q0 + q) * TKL;
        for (int k = lane; k < TKL; k += 32) {
            float p = s_sc[q][k] * inv;
            s_sc[q][k] = p;
            pout[k] = p;
        }
    }
    __syncthreads();

    const float* valb = values + (size_t)b * TKL * ND;
    const int n0 = tid * 2;
    float c0[4] = {0.f, 0.f, 0.f, 0.f};
    float c1[4] = {0.f, 0.f, 0.f, 0.f};
#pragma unroll 4
    for (int k = 0; k < TKL; k++) {
        float2 v = *(const float2*)(valb + (size_t)k * ND + n0);
#pragma unroll
        for (int q = 0; q < 4; q++) {
            float p = s_sc[q][k];
            c0[q] += p * v.x;
            c1[q] += p * v.y;
        }
    }
#pragma unroll
    for (int q = 0; q < 4; q++) {
        float* cp = g_ctx + (size_t)(b * TQL + q0 + q) * ND + n0;
        cp[0] = c0[q];
        cp[1] = c1[q];
    }
}

// ----------------------------------------------------------------------------
// Launch sequence (graph-capturable, allocation-free):
//   1) split-K GEMM: query @ W_q^T         -> g_part   (grid 8x8x4 = 256)
//   2) reduce + b_q                        -> g_attq
//   3) fused attention                     -> probs, g_ctx
//   4) split-K GEMM: [query|ctx] @ W_out^T -> g_part   (grid 8x8x4 = 256)
//   5) reduce + b_out + tanh               -> out
// ----------------------------------------------------------------------------
extern "C" void kernel_launch(void* const* d_in, const int* in_sizes, int n_in,
                              void* d_out, int out_size)
{
    const float* query  = (const float*)d_in[0];
    const float* keys   = (const float*)d_in[1];
    const float* values = (const float*)d_in[2];
    const float* W_q    = (const float*)d_in[3];
    const float* b_q    = (const float*)d_in[4];
    const float* w_att  = (const float*)d_in[5];
    const float* b_att  = (const float*)d_in[6];
    const float* W_out  = (const float*)d_in[7];
    const float* b_out  = (const float*)d_in[8];

    float* out   = (float*)d_out;
    float* probs = out + (size_t)MROWS * OD;

    gemm_nt_splitk<ND, 4, false><<<dim3(8, 8, 4), 256>>>(query, W_q);
    reduce_bias<4, false, true><<<256, 256>>>(b_q, nullptr);

    bahdanau_attn<<<MROWS / 4, 256>>>(keys, values, w_att, b_att, probs);

    gemm_nt_splitk<2 * ND, 4, true><<<dim3(8, 8, 4), 256>>>(query, W_out);
    reduce_bias<4, true, false><<<256, 256>>>(b_out, out);
}

// round 8
// speedup vs baseline: 1.5889x; 1.1129x over previous
#include <cuda_runtime.h>
#include <math.h>

#define BATCH 4
#define TQL   128
#define TKL   512
#define ND    512
#define OD    512
#define MROWS (BATCH * TQL)   // 512

// Scratch (device globals -- no allocation allowed)
__device__ __align__(16) float g_attq  [MROWS * ND];
__device__ __align__(16) float g_ctx   [MROWS * ND];
__device__ __align__(16) float g_scores[MROWS * TKL];
__device__ __align__(16) float g_part  [8 * MROWS * 512];   // split-K partials

__device__ __forceinline__ float fast_tanh(float x) {
    float y;
    asm("tanh.approx.f32 %0, %1;" : "=f"(y) : "f"(x));
    return y;
}

// ----------------------------------------------------------------------------
// Split-K NT GEMM: part[z][m][n] = sum_{k in chunk z} A[m,k] * B[n,k]
// 64x64 tile, BK=16, 256 threads, 4x4 micro-tile, double-buffered smem.
// SplitK=8 -> grid 8x8x8 = 512 blocks, 3 CTAs/SM allowed.
// ----------------------------------------------------------------------------
template <int K, int SPLITS, bool SECOND_IS_CTX>
__global__ __launch_bounds__(256, 3) void gemm_nt_splitk(
    const float* __restrict__ A0,
    const float* __restrict__ B)
{
    constexpr int CHUNK  = K / SPLITS;
    constexpr int STAGES = CHUNK / 16;

    __shared__ float As[2][16][68];
    __shared__ float Bs[2][16][68];

    const int tid = threadIdx.x;
    const int r   = tid >> 2;   // 0..63
    const int c   = tid & 3;    // 0..3
    const int ty  = tid >> 4;   // 0..15
    const int tx  = tid & 15;   // 0..15
    const int m0  = blockIdx.y * 64;
    const int n0  = blockIdx.x * 64;
    const int kst = blockIdx.z * CHUNK;

    float acc[4][4] = {};

    auto a_addr = [&](int kb) -> const float* {
        if (SECOND_IS_CTX && kb >= ND)
            return g_ctx + (size_t)(m0 + r) * ND + (kb - ND) + 4 * c;
        return A0 + (size_t)(m0 + r) * ND + kb + 4 * c;
    };

    float4 av = *(const float4*)a_addr(kst);
    float4 bv = *(const float4*)(B + (size_t)(n0 + r) * K + kst + 4 * c);
    {
        float a4[4] = {av.x, av.y, av.z, av.w};
        float b4[4] = {bv.x, bv.y, bv.z, bv.w};
#pragma unroll
        for (int j = 0; j < 4; j++) {
            As[0][4 * c + j][r] = a4[j];
            Bs[0][4 * c + j][r] = b4[j];
        }
    }
    __syncthreads();

    int buf = 0;
#pragma unroll 1
    for (int s = 0; s < STAGES; s++) {
        float4 anx, bnx;
        if (s + 1 < STAGES) {
            const int kb = kst + (s + 1) * 16;
            anx = *(const float4*)a_addr(kb);
            bnx = *(const float4*)(B + (size_t)(n0 + r) * K + kb + 4 * c);
        }

#pragma unroll
        for (int kk = 0; kk < 16; kk++) {
            float4 a = *(const float4*)&As[buf][kk][ty * 4];
            float4 b = *(const float4*)&Bs[buf][kk][tx * 4];
            float a4[4] = {a.x, a.y, a.z, a.w};
            float b4[4] = {b.x, b.y, b.z, b.w};
#pragma unroll
            for (int i = 0; i < 4; i++)
#pragma unroll
                for (int j = 0; j < 4; j++)
                    acc[i][j] += a4[i] * b4[j];
        }

        if (s + 1 < STAGES) {
            const int nb = buf ^ 1;
            float a4[4] = {anx.x, anx.y, anx.z, anx.w};
            float b4[4] = {bnx.x, bnx.y, bnx.z, bnx.w};
#pragma unroll
            for (int j = 0; j < 4; j++) {
                As[nb][4 * c + j][r] = a4[j];
                Bs[nb][4 * c + j][r] = b4[j];
            }
            __syncthreads();
            buf = nb;
        }
    }

    float* pp = g_part + (size_t)blockIdx.z * MROWS * 512;
#pragma unroll
    for (int i = 0; i < 4; i++) {
        float4 v = make_float4(acc[i][0], acc[i][1], acc[i][2], acc[i][3]);
        *(float4*)&pp[(size_t)(m0 + ty * 4 + i) * 512 + n0 + tx * 4] = v;
    }
}

// ----------------------------------------------------------------------------
// Split-K reduction + bias (+ optional accurate tanh on final output)
// ----------------------------------------------------------------------------
template <int SPLITS, bool DO_TANH, bool OUT_ATTQ>
__global__ __launch_bounds__(256) void reduce_bias(
    const float* __restrict__ bias,
    float* __restrict__ dext)
{
    float* dst = OUT_ATTQ ? g_attq : dext;
    const int idx = blockIdx.x * 256 + threadIdx.x;
    const float4* p = (const float4*)g_part;

    float4 s = p[idx];
#pragma unroll
    for (int sp = 1; sp < SPLITS; sp++) {
        float4 t = p[(size_t)sp * (MROWS * 512 / 4) + idx];
        s.x += t.x; s.y += t.y; s.z += t.z; s.w += t.w;
    }
    const float4 bb = ((const float4*)bias)[idx & (512 / 4 - 1)];
    s.x += bb.x; s.y += bb.y; s.z += bb.z; s.w += bb.w;
    if (DO_TANH) {
        s.x = tanhf(s.x); s.y = tanhf(s.y); s.z = tanhf(s.z); s.w = tanhf(s.w);
    }
    ((float4*)dst)[idx] = s;
}

// ----------------------------------------------------------------------------
// Scores kernel: grid 256 = b(4) x qgroup(32) x khalf(2); 256 threads.
// Block computes scores for 4 queries x 256 keys. Pure MUFU-tanh bound,
// covers the full chip. Writes raw scores (+b_att) to g_scores.
// ----------------------------------------------------------------------------
__global__ __launch_bounds__(256) void attn_scores(
    const float* __restrict__ keys,     // [B, TK, N]
    const float* __restrict__ w_att,    // [N]
    const float* __restrict__ b_att)    // [1]
{
    const int tid  = threadIdx.x;
    const int wid  = tid >> 5;
    const int lane = tid & 31;
    const int kh   = blockIdx.x & 1;
    const int q0   = ((blockIdx.x >> 1) & 31) << 2;
    const int b    = blockIdx.x >> 6;

    // Register-resident w_att and 4 att_query rows (lane owns 16 n-positions)
    float wreg[16];
    float areg[4][16];
#pragma unroll
    for (int i = 0; i < 4; i++) {
        float4 w4 = *(const float4*)(w_att + i * 128 + lane * 4);
        wreg[i * 4 + 0] = w4.x; wreg[i * 4 + 1] = w4.y;
        wreg[i * 4 + 2] = w4.z; wreg[i * 4 + 3] = w4.w;
#pragma unroll
        for (int q = 0; q < 4; q++) {
            float4 a4 = *(const float4*)(g_attq + (size_t)(b * TQL + q0 + q) * ND + i * 128 + lane * 4);
            areg[q][i * 4 + 0] = a4.x; areg[q][i * 4 + 1] = a4.y;
            areg[q][i * 4 + 2] = a4.z; areg[q][i * 4 + 3] = a4.w;
        }
    }
    const float batt = b_att[0];
    const float* keyb = keys + (size_t)b * TKL * ND;
    float* sco = g_scores + (size_t)(b * TQL + q0) * TKL;

    const int kend = kh * 256 + 256;
    for (int k = kh * 256 + wid; k < kend; k += 8) {
        const float* kr = keyb + (size_t)k * ND;
        float acc0 = 0.f, acc1 = 0.f, acc2 = 0.f, acc3 = 0.f;
#pragma unroll
        for (int i = 0; i < 4; i++) {
            float4 k4 = *(const float4*)(kr + i * 128 + lane * 4);
            float kv[4] = {k4.x, k4.y, k4.z, k4.w};
#pragma unroll
            for (int j = 0; j < 4; j++) {
                const float w = wreg[i * 4 + j];
                acc0 += w * fast_tanh(areg[0][i * 4 + j] + kv[j]);
                acc1 += w * fast_tanh(areg[1][i * 4 + j] + kv[j]);
                acc2 += w * fast_tanh(areg[2][i * 4 + j] + kv[j]);
                acc3 += w * fast_tanh(areg[3][i * 4 + j] + kv[j]);
            }
        }
#pragma unroll
        for (int off = 16; off; off >>= 1) {
            acc0 += __shfl_xor_sync(0xffffffffu, acc0, off);
            acc1 += __shfl_xor_sync(0xffffffffu, acc1, off);
            acc2 += __shfl_xor_sync(0xffffffffu, acc2, off);
            acc3 += __shfl_xor_sync(0xffffffffu, acc3, off);
        }
        if (lane == 0) {
            sco[0 * TKL + k] = acc0 + batt;
            sco[1 * TKL + k] = acc1 + batt;
            sco[2 * TKL + k] = acc2 + batt;
            sco[3 * TKL + k] = acc3 + batt;
        }
    }
}

// ----------------------------------------------------------------------------
// Softmax + context kernel: grid 256 = b(4) x qgroup(32) x nhalf(2).
// Softmax over full 512 keys per q (4 warps); probs written by nhalf==0.
// Context: each thread owns one of 256 value-columns, unroll-8 for MLP.
// ----------------------------------------------------------------------------
__global__ __launch_bounds__(256) void attn_smctx(
    const float* __restrict__ values,   // [B, TK, N]
    float* __restrict__ probs_out)      // [B, TQ, TK]
{
    __shared__ float s_sc[4 * TKL];     // 8 KB

    const int tid  = threadIdx.x;
    const int wid  = tid >> 5;
    const int lane = tid & 31;
    const int nh   = blockIdx.x & 1;
    const int q0   = ((blockIdx.x >> 1) & 31) << 2;
    const int b    = blockIdx.x >> 6;

    // Load 4x512 scores into smem (float4, coalesced)
    const float* sco = g_scores + (size_t)(b * TQL + q0) * TKL;
#pragma unroll
    for (int e = 0; e < 2; e++) {
        int f = tid + 256 * e;          // float4 index 0..511
        int q = f >> 7, off = (f & 127) * 4;
        *(float4*)&s_sc[q * TKL + off] = *(const float4*)(sco + q * TKL + off);
    }
    __syncthreads();

    // Softmax per q (warp q handles row q)
    if (wid < 4) {
        const int q = wid;
        float* row = s_sc + q * TKL;
        float m = -1e30f;
        for (int k = lane; k < TKL; k += 32) m = fmaxf(m, row[k]);
#pragma unroll
        for (int off = 16; off; off >>= 1) m = fmaxf(m, __shfl_xor_sync(0xffffffffu, m, off));
        float s = 0.f;
        for (int k = lane; k < TKL; k += 32) {
            float e = __expf(row[k] - m);
            row[k] = e;
            s += e;
        }
#pragma unroll
        for (int off = 16; off; off >>= 1) s += __shfl_xor_sync(0xffffffffu, s, off);
        const float inv = 1.0f / s;
        for (int k = lane; k < TKL; k += 32) row[k] *= inv;
        if (nh == 0) {
            float* pout = probs_out + (size_t)(b * TQL + q0 + q) * TKL;
            for (int k = lane; k < TKL; k += 32) pout[k] = row[k];
        }
    }
    __syncthreads();

    // Context: column n = nh*256 + tid
    const int n = nh * 256 + tid;
    const float* vp = values + (size_t)b * TKL * ND + n;
    float c[4] = {0.f, 0.f, 0.f, 0.f};
#pragma unroll 8
    for (int k = 0; k < TKL; k++) {
        float v = vp[(size_t)k * ND];
#pragma unroll
        for (int q = 0; q < 4; q++) c[q] += s_sc[q * TKL + k] * v;
    }
#pragma unroll
    for (int q = 0; q < 4; q++)
        g_ctx[(size_t)(b * TQL + q0 + q) * ND + n] = c[q];
}

// ----------------------------------------------------------------------------
// Launch sequence (graph-capturable, allocation-free)
// ----------------------------------------------------------------------------
extern "C" void kernel_launch(void* const* d_in, const int* in_sizes, int n_in,
                              void* d_out, int out_size)
{
    const float* query  = (const float*)d_in[0];
    const float* keys   = (const float*)d_in[1];
    const float* values = (const float*)d_in[2];
    const float* W_q    = (const float*)d_in[3];
    const float* b_q    = (const float*)d_in[4];
    const float* w_att  = (const float*)d_in[5];
    const float* b_att  = (const float*)d_in[6];
    const float* W_out  = (const float*)d_in[7];
    const float* b_out  = (const float*)d_in[8];

    float* out   = (float*)d_out;
    float* probs = out + (size_t)MROWS * OD;

    gemm_nt_splitk<ND, 8, false><<<dim3(8, 8, 8), 256>>>(query, W_q);
    reduce_bias<8, false, true><<<256, 256>>>(b_q, nullptr);

    attn_scores<<<256, 256>>>(keys, w_att, b_att);
    attn_smctx<<<256, 256>>>(values, probs);

    gemm_nt_splitk<2 * ND, 8, true><<<dim3(8, 8, 8), 256>>>(query, W_out);
    reduce_bias<8, true, false><<<256, 256>>>(b_out, out);
}

// round 9
// speedup vs baseline: 1.8447x; 1.1610x over previous
#include <cuda_runtime.h>
#include <math.h>

#define BATCH 4
#define TQL   128
#define TKL   512
#define ND    512
#define OD    512
#define MROWS (BATCH * TQL)   // 512

// Scratch (device globals -- no allocation allowed)
__device__ __align__(16) float g_attq  [MROWS * ND];
__device__ __align__(16) float g_ctx   [MROWS * ND];
__device__ __align__(16) float g_scores[MROWS * TKL];
__device__ __align__(16) float g_part  [8 * MROWS * 512];   // split-K partials

__device__ __forceinline__ float fast_tanh(float x) {
    float y;
    asm("tanh.approx.f32 %0, %1;" : "=f"(y) : "f"(x));
    return y;
}

// ----------------------------------------------------------------------------
// Split-K NT GEMM (A,B both row-major with K contiguous):
//   part[z][m][n] = sum_{k in chunk z} A[m,k] * B[n,k]
// 64x64 tile, BK=16, 256 threads, 4x4 micro-tile, double-buffered smem.
// ----------------------------------------------------------------------------
template <int K, int SPLITS, bool SECOND_IS_CTX>
__global__ __launch_bounds__(256, 3) void gemm_nt_splitk(
    const float* __restrict__ A0,
    const float* __restrict__ B)
{
    constexpr int CHUNK  = K / SPLITS;
    constexpr int STAGES = CHUNK / 16;

    __shared__ float As[2][16][68];
    __shared__ float Bs[2][16][68];

    const int tid = threadIdx.x;
    const int r   = tid >> 2;   // 0..63
    const int c   = tid & 3;    // 0..3
    const int ty  = tid >> 4;   // 0..15
    const int tx  = tid & 15;   // 0..15
    const int m0  = blockIdx.y * 64;
    const int n0  = blockIdx.x * 64;
    const int kst = blockIdx.z * CHUNK;

    float acc[4][4] = {};

    auto a_addr = [&](int kb) -> const float* {
        if (SECOND_IS_CTX && kb >= ND)
            return g_ctx + (size_t)(m0 + r) * ND + (kb - ND) + 4 * c;
        return A0 + (size_t)(m0 + r) * ND + kb + 4 * c;
    };

    float4 av = *(const float4*)a_addr(kst);
    float4 bv = *(const float4*)(B + (size_t)(n0 + r) * K + kst + 4 * c);
    {
        float a4[4] = {av.x, av.y, av.z, av.w};
        float b4[4] = {bv.x, bv.y, bv.z, bv.w};
#pragma unroll
        for (int j = 0; j < 4; j++) {
            As[0][4 * c + j][r] = a4[j];
            Bs[0][4 * c + j][r] = b4[j];
        }
    }
    __syncthreads();

    int buf = 0;
#pragma unroll 1
    for (int s = 0; s < STAGES; s++) {
        float4 anx, bnx;
        if (s + 1 < STAGES) {
            const int kb = kst + (s + 1) * 16;
            anx = *(const float4*)a_addr(kb);
            bnx = *(const float4*)(B + (size_t)(n0 + r) * K + kb + 4 * c);
        }

#pragma unroll
        for (int kk = 0; kk < 16; kk++) {
            float4 a = *(const float4*)&As[buf][kk][ty * 4];
            float4 b = *(const float4*)&Bs[buf][kk][tx * 4];
            float a4[4] = {a.x, a.y, a.z, a.w};
            float b4[4] = {b.x, b.y, b.z, b.w};
#pragma unroll
            for (int i = 0; i < 4; i++)
#pragma unroll
                for (int j = 0; j < 4; j++)
                    acc[i][j] += a4[i] * b4[j];
        }

        if (s + 1 < STAGES) {
            const int nb = buf ^ 1;
            float a4[4] = {anx.x, anx.y, anx.z, anx.w};
            float b4[4] = {bnx.x, bnx.y, bnx.z, bnx.w};
#pragma unroll
            for (int j = 0; j < 4; j++) {
                As[nb][4 * c + j][r] = a4[j];
                Bs[nb][4 * c + j][r] = b4[j];
            }
            __syncthreads();
            buf = nb;
        }
    }

    float* pp = g_part + (size_t)blockIdx.z * MROWS * 512;
#pragma unroll
    for (int i = 0; i < 4; i++) {
        float4 v = make_float4(acc[i][0], acc[i][1], acc[i][2], acc[i][3]);
        *(float4*)&pp[(size_t)(m0 + ty * 4 + i) * 512 + n0 + tx * 4] = v;
    }
}

// ----------------------------------------------------------------------------
// Split-K NN GEMM for context: part[z][m][n] = sum_k P[m,k] * V_b[k,n]
// P = probs (row-major [MROWS, TKL]); V_b = values of batch (m0>>7), [TKL, ND].
// Same 64x64 / BK=16 / 4x4 micro-kernel; only the B-tile load differs.
// ----------------------------------------------------------------------------
template <int SPLITS>
__global__ __launch_bounds__(256, 3) void gemm_ctx_splitk(
    const float* __restrict__ P,
    const float* __restrict__ values)
{
    constexpr int CHUNK  = TKL / SPLITS;
    constexpr int STAGES = CHUNK / 16;

    __shared__ float As[2][16][68];
    __shared__ float Bs[2][16][68];

    const int tid = threadIdx.x;
    const int r   = tid >> 2;   // 0..63 (A row)
    const int c   = tid & 3;    // 0..3  (A k-group)
    const int bk  = tid >> 4;   // 0..15 (B k row)
    const int bn  = (tid & 15) * 4; // B col group
    const int ty  = tid >> 4;
    const int tx  = tid & 15;
    const int m0  = blockIdx.y * 64;
    const int n0  = blockIdx.x * 64;
    const int kst = blockIdx.z * CHUNK;

    const float* valb = values + (size_t)(m0 >> 7) * TKL * ND;

    float acc[4][4] = {};

    // prologue
    {
        float4 av = *(const float4*)(P + (size_t)(m0 + r) * TKL + kst + 4 * c);
        float4 bvv = *(const float4*)(valb + (size_t)(kst + bk) * ND + n0 + bn);
        float a4[4] = {av.x, av.y, av.z, av.w};
#pragma unroll
        for (int j = 0; j < 4; j++) As[0][4 * c + j][r] = a4[j];
        *(float4*)&Bs[0][bk][bn] = bvv;
    }
    __syncthreads();

    int buf = 0;
#pragma unroll 1
    for (int s = 0; s < STAGES; s++) {
        float4 anx, bnx;
        if (s + 1 < STAGES) {
            const int kb = kst + (s + 1) * 16;
            anx = *(const float4*)(P + (size_t)(m0 + r) * TKL + kb + 4 * c);
            bnx = *(const float4*)(valb + (size_t)(kb + bk) * ND + n0 + bn);
        }

#pragma unroll
        for (int kk = 0; kk < 16; kk++) {
            float4 a = *(const float4*)&As[buf][kk][ty * 4];
            float4 b = *(const float4*)&Bs[buf][kk][tx * 4];
            float a4[4] = {a.x, a.y, a.z, a.w};
            float b4[4] = {b.x, b.y, b.z, b.w};
#pragma unroll
            for (int i = 0; i < 4; i++)
#pragma unroll
                for (int j = 0; j < 4; j++)
                    acc[i][j] += a4[i] * b4[j];
        }

        if (s + 1 < STAGES) {
            const int nb = buf ^ 1;
            float a4[4] = {anx.x, anx.y, anx.z, anx.w};
#pragma unroll
            for (int j = 0; j < 4; j++) As[nb][4 * c + j][r] = a4[j];
            *(float4*)&Bs[nb][bk][bn] = bnx;
            __syncthreads();
            buf = nb;
        }
    }

    float* pp = g_part + (size_t)blockIdx.z * MROWS * 512;
#pragma unroll
    for (int i = 0; i < 4; i++) {
        float4 v = make_float4(acc[i][0], acc[i][1], acc[i][2], acc[i][3]);
        *(float4*)&pp[(size_t)(m0 + ty * 4 + i) * 512 + n0 + tx * 4] = v;
    }
}

// ----------------------------------------------------------------------------
// Split-K reduction. MODE: 0 = +bias -> g_attq; 1 = +bias, tanh -> dext;
//                          2 = no bias -> g_ctx
// ----------------------------------------------------------------------------
template <int SPLITS, int MODE>
__global__ __launch_bounds__(256) void reduce_part(
    const float* __restrict__ bias,
    float* __restrict__ dext)
{
    float* dst = (MODE == 0) ? g_attq : (MODE == 2) ? g_ctx : dext;
    const int idx = blockIdx.x * 256 + threadIdx.x;
    const float4* p = (const float4*)g_part;

    float4 s = p[idx];
#pragma unroll
    for (int sp = 1; sp < SPLITS; sp++) {
        float4 t = p[(size_t)sp * (MROWS * 512 / 4) + idx];
        s.x += t.x; s.y += t.y; s.z += t.z; s.w += t.w;
    }
    if (MODE != 2) {
        const float4 bb = ((const float4*)bias)[idx & (512 / 4 - 1)];
        s.x += bb.x; s.y += bb.y; s.z += bb.z; s.w += bb.w;
    }
    if (MODE == 1) {
        s.x = tanhf(s.x); s.y = tanhf(s.y); s.z = tanhf(s.z); s.w = tanhf(s.w);
    }
    ((float4*)dst)[idx] = s;
}

// ----------------------------------------------------------------------------
// Scores kernel: grid 256 = khalf(2) x qgroup(32) x b(4); 256 threads.
// Block computes scores for 4 queries x 256 keys. MUFU-tanh bound.
// ----------------------------------------------------------------------------
__global__ __launch_bounds__(256) void attn_scores(
    const float* __restrict__ keys,
    const float* __restrict__ w_att,
    const float* __restrict__ b_att)
{
    const int tid  = threadIdx.x;
    const int wid  = tid >> 5;
    const int lane = tid & 31;
    const int kh   = blockIdx.x & 1;
    const int q0   = ((blockIdx.x >> 1) & 31) << 2;
    const int b    = blockIdx.x >> 6;

    float wreg[16];
    float areg[4][16];
#pragma unroll
    for (int i = 0; i < 4; i++) {
        float4 w4 = *(const float4*)(w_att + i * 128 + lane * 4);
        wreg[i * 4 + 0] = w4.x; wreg[i * 4 + 1] = w4.y;
        wreg[i * 4 + 2] = w4.z; wreg[i * 4 + 3] = w4.w;
#pragma unroll
        for (int q = 0; q < 4; q++) {
            float4 a4 = *(const float4*)(g_attq + (size_t)(b * TQL + q0 + q) * ND + i * 128 + lane * 4);
            areg[q][i * 4 + 0] = a4.x; areg[q][i * 4 + 1] = a4.y;
            areg[q][i * 4 + 2] = a4.z; areg[q][i * 4 + 3] = a4.w;
        }
    }
    const float batt = b_att[0];
    const float* keyb = keys + (size_t)b * TKL * ND;
    float* sco = g_scores + (size_t)(b * TQL + q0) * TKL;

    const int kend = kh * 256 + 256;
    for (int k = kh * 256 + wid; k < kend; k += 8) {
        const float* kr = keyb + (size_t)k * ND;
        float acc0 = 0.f, acc1 = 0.f, acc2 = 0.f, acc3 = 0.f;
#pragma unroll
        for (int i = 0; i < 4; i++) {
            float4 k4 = *(const float4*)(kr + i * 128 + lane * 4);
            float kv[4] = {k4.x, k4.y, k4.z, k4.w};
#pragma unroll
            for (int j = 0; j < 4; j++) {
                const float w = wreg[i * 4 + j];
                acc0 += w * fast_tanh(areg[0][i * 4 + j] + kv[j]);
                acc1 += w * fast_tanh(areg[1][i * 4 + j] + kv[j]);
                acc2 += w * fast_tanh(areg[2][i * 4 + j] + kv[j]);
                acc3 += w * fast_tanh(areg[3][i * 4 + j] + kv[j]);
            }
        }
#pragma unroll
        for (int off = 16; off; off >>= 1) {
            acc0 += __shfl_xor_sync(0xffffffffu, acc0, off);
            acc1 += __shfl_xor_sync(0xffffffffu, acc1, off);
            acc2 += __shfl_xor_sync(0xffffffffu, acc2, off);
            acc3 += __shfl_xor_sync(0xffffffffu, acc3, off);
        }
        if (lane == 0) {
            sco[0 * TKL + k] = acc0 + batt;
            sco[1 * TKL + k] = acc1 + batt;
            sco[2 * TKL + k] = acc2 + batt;
            sco[3 * TKL + k] = acc3 + batt;
        }
    }
}

// ----------------------------------------------------------------------------
// Row softmax: one warp per query row, register-resident (16 floats/lane).
// Reads g_scores, writes probs (output buffer). Grid 64 x 256 threads.
// ----------------------------------------------------------------------------
__global__ __launch_bounds__(256) void softmax_rows(float* __restrict__ probs)
{
    const int wid  = threadIdx.x >> 5;
    const int lane = threadIdx.x & 31;
    const int row  = blockIdx.x * 8 + wid;

    const float* src = g_scores + (size_t)row * TKL;
    float v[16];
    float m = -1e30f;
#pragma unroll
    for (int i = 0; i < 4; i++) {
        float4 t = *(const float4*)(src + i * 128 + lane * 4);
        v[i * 4 + 0] = t.x; v[i * 4 + 1] = t.y; v[i * 4 + 2] = t.z; v[i * 4 + 3] = t.w;
        m = fmaxf(m, fmaxf(fmaxf(t.x, t.y), fmaxf(t.z, t.w)));
    }
#pragma unroll
    for (int off = 16; off; off >>= 1) m = fmaxf(m, __shfl_xor_sync(0xffffffffu, m, off));
    float s = 0.f;
#pragma unroll
    for (int i = 0; i < 16; i++) {
        v[i] = __expf(v[i] - m);
        s += v[i];
    }
#pragma unroll
    for (int off = 16; off; off >>= 1) s += __shfl_xor_sync(0xffffffffu, s, off);
    const float inv = 1.0f / s;
    float* dst = probs + (size_t)row * TKL;
#pragma unroll
    for (int i = 0; i < 4; i++) {
        float4 t = make_float4(v[i * 4 + 0] * inv, v[i * 4 + 1] * inv,
                               v[i * 4 + 2] * inv, v[i * 4 + 3] * inv);
        *(float4*)(dst + i * 128 + lane * 4) = t;
    }
}

// ----------------------------------------------------------------------------
// Launch sequence (graph-capturable, allocation-free)
// ----------------------------------------------------------------------------
extern "C" void kernel_launch(void* const* d_in, const int* in_sizes, int n_in,
                              void* d_out, int out_size)
{
    const float* query  = (const float*)d_in[0];
    const float* keys   = (const float*)d_in[1];
    const float* values = (const float*)d_in[2];
    const float* W_q    = (const float*)d_in[3];
    const float* b_q    = (const float*)d_in[4];
    const float* w_att  = (const float*)d_in[5];
    const float* b_att  = (const float*)d_in[6];
    const float* W_out  = (const float*)d_in[7];
    const float* b_out  = (const float*)d_in[8];

    float* out   = (float*)d_out;
    float* probs = out + (size_t)MROWS * OD;

    // 1) att_query = query @ W_q^T + b_q
    gemm_nt_splitk<ND, 8, false><<<dim3(8, 8, 8), 256>>>(query, W_q);
    reduce_part<8, 0><<<256, 256>>>(b_q, nullptr);

    // 2) scores -> softmax -> probs (written directly to output)
    attn_scores<<<256, 256>>>(keys, w_att, b_att);
    softmax_rows<<<64, 256>>>(probs);

    // 3) context = probs @ values (per-batch NN GEMM, split-K)
    gemm_ctx_splitk<8><<<dim3(8, 8, 8), 256>>>(probs, values);
    reduce_part<8, 2><<<256, 256>>>(nullptr, nullptr);

    // 4) out = tanh([query|ctx] @ W_out^T + b_out)
    gemm_nt_splitk<2 * ND, 8, true><<<dim3(8, 8, 8), 256>>>(query, W_out);
    reduce_part<8, 1><<<256, 256>>>(b_out, out);
}